// round 16
// baseline (speedup 1.0000x reference)
#include <cuda_runtime.h>
#include <math.h>
#include <stdint.h>

#define NB   8
#define NT   500
#define NF   257
#define NC   8
#define NNUL 4
#define LOWF 5
#define HIGHF 70
#define DCF_SIZE (NB*NT*NF*NNUL)

#define OMA   0.65f
#define AOVER 0.53846156f           // a/(1-a)

#define NFG   33                    // ceil(257/8) f-groups of 8
#define NCHUNK 4                    // t chunks of 128

#define ROWF  (NF*NC)               // 2056 floats per (bt,part) row
#define XROW  132                   // xs row: 2*64 + 4 pad
#define XSBUF (32*XROW)             // floats per xs buffer

// ---------------- scratch (k_rat leaves accums zeroed for next replay) ------
__device__ float g_pre[NB*NT];
__device__ float g_aft[NB*NT*NNUL];
__device__ float g_rat[NB*NT*NNUL];

// ---------------- cp.async helpers -------------------------------------------
__device__ __forceinline__ void cp16(uint32_t dst, const float* src) {
    asm volatile("cp.async.cg.shared.global [%0], [%1], 16;" :: "r"(dst), "l"(src));
}
__device__ __forceinline__ void cp_commit() {
    asm volatile("cp.async.commit_group;");
}

// ---------------- decayed Kogge-Stone over 32 lanes --------------------------
__device__ __forceinline__ void scan9(float u[9], int lane) {
    const float AJ0=0.35f, AJ1=0.1225f, AJ2=0.01500625f,
                AJ3=2.25187539e-4f, AJ4=5.07094278e-8f;
    #pragma unroll
    for (int kk = 0; kk < 9; kk++) {
        float v;
        v = __shfl_up_sync(0xffffffffu, u[kk], 1);  if (lane>=1)  u[kk]=fmaf(AJ0,v,u[kk]);
        v = __shfl_up_sync(0xffffffffu, u[kk], 2);  if (lane>=2)  u[kk]=fmaf(AJ1,v,u[kk]);
        v = __shfl_up_sync(0xffffffffu, u[kk], 4);  if (lane>=4)  u[kk]=fmaf(AJ2,v,u[kk]);
        v = __shfl_up_sync(0xffffffffu, u[kk], 8);  if (lane>=8)  u[kk]=fmaf(AJ3,v,u[kk]);
        v = __shfl_up_sync(0xffffffffu, u[kk], 16); if (lane>=16) u[kk]=fmaf(AJ4,v,u[kk]);
    }
}

// =================== k_main: 256 threads, 8 f's per block ====================
// grid = (b*4 + chunk)*33 + fgrp ; block = 256 (8 warps = 8 consecutive f)
__global__ __launch_bounds__(256, 3)
void k_main(const float* __restrict__ in, const int* __restrict__ beam_id,
            const float* __restrict__ tw, const float* __restrict__ nw,
            float* __restrict__ out) {
    __shared__ __align__(16) float xs[2][32][XROW];  // double-buffered staging
    __shared__ float  wsm[8][80];     // per-warp weights: [w][16 targ | 64 null]
    __shared__ float4 q_s[8][34];     // 34-pad: conflict-free staged reads
    __shared__ float2 tg_s[8][34];
    __shared__ int    fs_s[8], fv_s[8];

    int bi    = blockIdx.x;
    int fgrp  = bi % NFG;
    int rem   = bi / NFG;
    int chunk = rem & 3;
    int b     = rem >> 2;

    int tid = threadIdx.x, lane = tid & 31, w = tid >> 5;
    int f0  = fgrp * 8;
    int fv  = (f0 + w) < NF;
    int f   = min(f0 + w, NF-1);
    int beam = beam_id[b];
    bool inb = fv && (f >= LOWF) && (f < HIGHF);

    if (lane == 0) { fs_s[w] = f; fv_s[w] = fv; }

    // ---- stage weights (once) ----
    if (lane < 16) {   // target: 8f x [part(2)][c(8)]
        int part = lane >> 3, c = lane & 7;
        wsm[w][part*8 + c] = tw[((beam*2 + part)*NF + f)*NC + c];
    }
    {   // nulls: 8f x 64 = 512 floats, 2 per thread; wsm[w][16 + (n*2+ri)*8+c]
        #pragma unroll
        for (int h = 0; h < 2; h++) {
            int j = lane + h*32;
            int n = j >> 4, ri = (j >> 3) & 1, c = j & 7;
            wsm[w][16 + j] = nw[(((beam*NNUL + n)*2 + ri)*NF + f)*NC + c];
        }
    }
    __syncthreads();

    float pa = exp2f((float)(lane+1) * -1.5145732f);   // a^(lane+1)
    float carry[9];
    #pragma unroll
    for (int k = 0; k < 9; k++) carry[k] = 0.0f;

    // ---- per-pass staging constants (4 cp.async tasks per thread) ----
    // tasks: 32t x 2part x 16 float4 (8f x 8c = 64 floats per (t,part))
    const int ROWLIM = ROWF - 4;
    int tl_[4];
    uint32_t dst_[4];
    const float* pbase_[4];
    {
        uint32_t xs0 = (uint32_t)__cvta_generic_to_shared(&xs[0][0][0]);
        const float* inb0 = in + (size_t)b*NT*2*ROWF;
        #pragma unroll
        for (int pass = 0; pass < 4; pass++) {
            int i   = pass*256 + tid;       // 0..1023
            int seg = i >> 4;               // 0..63 = tl*2 + part
            int tl  = seg >> 1, part = seg & 1, e = i & 15;
            int col = min(f0*NC + e*4, ROWLIM);
            tl_[pass]    = tl;
            dst_[pass]   = xs0 + (uint32_t)(tl*XROW + part*64 + e*4)*4;
            pbase_[pass] = inb0 + (size_t)part*ROWF + col;
        }
    }

    int T0 = chunk * 128;
    int itstart = chunk ? -1 : 0;       // it = -1 is warmup (discard)

    // ---- prologue: stage first iteration into buf (itstart & 1) ----
    {
        int tbase = T0 + itstart*32;
        uint32_t bofs = (uint32_t)(itstart & 1) * (XSBUF*4);
        #pragma unroll
        for (int pass = 0; pass < 4; pass++) {
            int tg = min(tbase + tl_[pass], NT-1);
            cp16(dst_[pass] + bofs, pbase_[pass] + (size_t)tg*2*ROWF);
        }
        cp_commit();
    }

    for (int it = itstart; it < 4; it++) {
        int tbase = T0 + it*32;
        int buf   = it & 1;

        // ---- issue next iteration's group (overlaps current compute) ----
        if (it < 3) {
            int tnext = tbase + 32;
            uint32_t bofs = (uint32_t)((it+1) & 1) * (XSBUF*4);
            #pragma unroll
            for (int pass = 0; pass < 4; pass++) {
                int tg = min(tnext + tl_[pass], NT-1);
                cp16(dst_[pass] + bofs, pbase_[pass] + (size_t)tg*2*ROWF);
            }
            cp_commit();
            asm volatile("cp.async.wait_group 1;");
        } else {
            asm volatile("cp.async.wait_group 0;");
        }
        __syncthreads();                // current buffer fully staged, visible

        // ---- beamform from smem ----
        float xr[8], xi[8];
        {
            float4 r0 = *(float4*)&xs[buf][lane][w*8];
            float4 r1 = *(float4*)&xs[buf][lane][w*8 + 4];
            float4 i0 = *(float4*)&xs[buf][lane][64 + w*8];
            float4 i1 = *(float4*)&xs[buf][lane][64 + w*8 + 4];
            xr[0]=r0.x; xr[1]=r0.y; xr[2]=r0.z; xr[3]=r0.w;
            xr[4]=r1.x; xr[5]=r1.y; xr[6]=r1.z; xr[7]=r1.w;
            xi[0]=i0.x; xi[1]=i0.y; xi[2]=i0.z; xi[3]=i0.w;
            xi[4]=i1.x; xi[5]=i1.y; xi[6]=i1.z; xi[7]=i1.w;
        }

        // target weights via uniform smem loads
        float tr=0.f, ti=0.f, pw=0.f;
        {
            float4 a0 = *(float4*)&wsm[w][0], a1 = *(float4*)&wsm[w][4];
            float4 b0 = *(float4*)&wsm[w][8], b1 = *(float4*)&wsm[w][12];
            float twr_[8], twi_[8];
            twr_[0]=a0.x; twr_[1]=a0.y; twr_[2]=a0.z; twr_[3]=a0.w;
            twr_[4]=a1.x; twr_[5]=a1.y; twr_[6]=a1.z; twr_[7]=a1.w;
            twi_[0]=b0.x; twi_[1]=b0.y; twi_[2]=b0.z; twi_[3]=b0.w;
            twi_[4]=b1.x; twi_[5]=b1.y; twi_[6]=b1.z; twi_[7]=b1.w;
            #pragma unroll
            for (int c = 0; c < 8; c++) {
                tr = fmaf(twr_[c], xr[c], tr); tr = fmaf(-twi_[c], xi[c], tr);
                ti = fmaf(twi_[c], xr[c], ti); ti = fmaf( twr_[c], xi[c], ti);
                pw = fmaf(xr[c], xr[c], pw);  pw = fmaf(xi[c], xi[c], pw);
            }
        }
        pw *= 0.125f;

        int t = tbase + lane;
        float u[9];
        #pragma unroll
        for (int n = 0; n < NNUL; n++) {
            float nwr_[8], nwi_[8];
            {
                float4 c0 = *(float4*)&wsm[w][16 + n*16];
                float4 c1 = *(float4*)&wsm[w][16 + n*16 + 4];
                float4 d0 = *(float4*)&wsm[w][16 + n*16 + 8];
                float4 d1 = *(float4*)&wsm[w][16 + n*16 + 12];
                nwr_[0]=c0.x; nwr_[1]=c0.y; nwr_[2]=c0.z; nwr_[3]=c0.w;
                nwr_[4]=c1.x; nwr_[5]=c1.y; nwr_[6]=c1.z; nwr_[7]=c1.w;
                nwi_[0]=d0.x; nwi_[1]=d0.y; nwi_[2]=d0.z; nwi_[3]=d0.w;
                nwi_[4]=d1.x; nwi_[5]=d1.y; nwi_[6]=d1.z; nwi_[7]=d1.w;
            }
            float nr=0.f, ni=0.f;
            #pragma unroll
            for (int c = 0; c < 8; c++) {
                nr = fmaf(nwr_[c], xr[c], nr); nr = fmaf(-nwi_[c], xi[c], nr);
                ni = fmaf(nwi_[c], xr[c], ni); ni = fmaf( nwr_[c], xi[c], ni);
            }
            float pr = tr*nr + ti*ni;
            float pi = ti*nr - tr*ni;
            if (t == 0) {   // reference's t=0 quirk (chunk 0, iter 0, lane 0)
                pr = fmaf( AOVER*ti, ni, pr);
                pi = fmaf(-AOVER*tr, ni, pi);
            }
            u[n]   = OMA*pr;
            u[4+n] = OMA*pi;
        }
        u[8] = OMA*pw;

        scan9(u, lane);
        float y[9];
        #pragma unroll
        for (int k = 0; k < 9; k++) y[k] = fmaf(pa, carry[k], u[k]);
        #pragma unroll
        for (int k = 0; k < 9; k++) carry[k] = __shfl_sync(0xffffffffu, y[k], 31);

        if (it < 0) continue;           // warmup: discard (xs buffers disjoint)

        // ---- epilogue: pre-ratio q, band atomics, staged coalesced stores --
        float rinv = __fdividef(1.0f, y[8] + 1e-13f);
        float ph[4], q[4];
        #pragma unroll
        for (int n = 0; n < 4; n++) {
            ph[n] = sqrtf(fmaf(y[n], y[n], y[4+n]*y[4+n]));
            q[n]  = fminf(fmaxf(ph[n]*rinv, 0.01f), 1.0f);
        }
        if (inb && t < NT) {
            atomicAdd(g_pre + b*NT + t, y[8]);
            float* aftp = g_aft + (b*NT + t)*NNUL;
            #pragma unroll
            for (int n = 0; n < 4; n++) atomicAdd(aftp + n, ph[n]);
        }

        q_s[w][lane]  = make_float4(q[0], q[1], q[2], q[3]);
        tg_s[w][lane] = make_float2(tr, ti);
        __syncthreads();                // q_s/tg_s writes visible to readers

        {   // dcf: task = (t_local 32, fi 8); 128B contiguous runs per t
            int tl = tid >> 3, fi = tid & 7;
            int tt = tbase + tl;
            if (fv_s[fi] && tt < NT)
                *(float4*)(out + ((size_t)(b*NT + tt)*NF + fs_s[fi])*4) = q_s[fi][tl];
        }
        {   // targ: task = (part, t_local, f-pair); 2 scalars each
            int p = tid >> 7, r2 = tid & 127, tl2 = r2 >> 2, f2 = (r2 & 3)*2;
            int tt2 = tbase + tl2;
            if (tt2 < NT) {
                size_t base = DCF_SIZE + ((size_t)(b*NT + tt2)*2 + p)*NF;
                #pragma unroll
                for (int h = 0; h < 2; h++) {
                    if (fv_s[f2+h]) {
                        float2 v = tg_s[f2+h][tl2];
                        out[base + fs_s[f2+h]] = p ? v.y : v.x;
                    }
                }
            }
        }
        // q_s reads are fenced by next iteration's wait+syncthreads.
    }
}

// =================== k_rat: ratios + accumulator reset =======================
__global__ __launch_bounds__(256)
void k_rat(void) {
    int idx = blockIdx.x*256 + threadIdx.x;
    if (idx >= NB*NT) return;
    float pre = g_pre[idx];
    float4 af = ((const float4*)g_aft)[idx];
    float pinv = __fdividef(1.0f, pre + 1e-10f);
    float4 r;
    r.x = fminf(fmaxf(af.x*pinv, 0.01f), 1.0f);
    r.y = fminf(fmaxf(af.y*pinv, 0.01f), 1.0f);
    r.z = fminf(fmaxf(af.z*pinv, 0.01f), 1.0f);
    r.w = fminf(fmaxf(af.w*pinv, 0.01f), 1.0f);
    ((float4*)g_rat)[idx] = r;
    g_pre[idx] = 0.0f;
    ((float4*)g_aft)[idx] = make_float4(0.f, 0.f, 0.f, 0.f);
}

// =================== k_fix_flat: streaming ratio apply (t >= 1) ==============
__global__ __launch_bounds__(256)
void k_fix_flat(float* __restrict__ out) {
    int idx = blockIdx.x*256 + threadIdx.x;     // one per (b,t,f)
    if (idx >= NB*NT*NF) return;
    int bt = idx / NF;
    int t  = bt % NT;
    if (t == 0) return;
    float4 rat = ((const float4*)g_rat)[bt];
    float* p = out + (size_t)idx*4;
    float4 q = *(float4*)p;
    q.x = sqrtf(q.x * rat.x);
    q.y = sqrtf(q.y * rat.y);
    q.z = sqrtf(q.z * rat.z);
    q.w = sqrtf(q.w * rat.w);
    *(float4*)p = q;
}

// =================== launcher ===============================================
extern "C" void kernel_launch(void* const* d_in, const int* in_sizes, int n_in,
                              void* d_out, int out_size) {
    const float* in      = (const float*)d_in[0];
    const int*   beam_id = (const int*)  d_in[1];
    const float* tw      = (const float*)d_in[2];
    const float* nw      = (const float*)d_in[3];
    float* out = (float*)d_out;

    k_main<<<NB*NCHUNK*NFG, 256>>>(in, beam_id, tw, nw, out);
    k_rat<<<(NB*NT + 255)/256, 256>>>();
    k_fix_flat<<<(NB*NT*NF + 255)/256, 256>>>(out);
}

// round 17
// speedup vs baseline: 1.1251x; 1.1251x over previous
#include <cuda_runtime.h>
#include <math.h>
#include <stdint.h>

#define NB   8
#define NT   500
#define NF   257
#define NC   8
#define NNUL 4
#define LOWF 5
#define HIGHF 70
#define DCF_SIZE (NB*NT*NF*NNUL)

#define OMA   0.65f
#define AOVER 0.53846156f           // a/(1-a)

#define NFG   65                    // ceil(257/4) f-groups
#define NCHUNK 4                    // t chunks of 128 (grid 2080: >2 waves)

#define ROWF  (NF*NC)               // 2056 floats per (bt,part) row
#define XSBUF (32*68)               // floats per xs buffer

// ---------------- scratch (k_rat leaves accums zeroed for next replay) ------
__device__ float g_pre[NB*NT];
__device__ float g_aft[NB*NT*NNUL];
__device__ float g_rat[NB*NT*NNUL];

// ---------------- cp.async helpers -------------------------------------------
__device__ __forceinline__ void cp16(uint32_t dst, const float* src) {
    asm volatile("cp.async.cg.shared.global [%0], [%1], 16;" :: "r"(dst), "l"(src));
}
__device__ __forceinline__ void cp_commit() {
    asm volatile("cp.async.commit_group;");
}

// ---------------- truncated decayed Kogge-Stone (4 stages; a^16=5e-8 dropped)
__device__ __forceinline__ void scan9(float u[9], int lane) {
    const float AJ0=0.35f, AJ1=0.1225f, AJ2=0.01500625f, AJ3=2.25187539e-4f;
    #pragma unroll
    for (int kk = 0; kk < 9; kk++) {
        float v;
        v = __shfl_up_sync(0xffffffffu, u[kk], 1);  if (lane>=1)  u[kk]=fmaf(AJ0,v,u[kk]);
        v = __shfl_up_sync(0xffffffffu, u[kk], 2);  if (lane>=2)  u[kk]=fmaf(AJ1,v,u[kk]);
        v = __shfl_up_sync(0xffffffffu, u[kk], 4);  if (lane>=4)  u[kk]=fmaf(AJ2,v,u[kk]);
        v = __shfl_up_sync(0xffffffffu, u[kk], 8);  if (lane>=8)  u[kk]=fmaf(AJ3,v,u[kk]);
        // stage d=16 dropped: coeff a^16 = 5.07e-8 << 1e-3 tolerance
    }
}

// =================== k_main: R15 + truncated scan + hoisted store indices ====
// grid = (b*4 + chunk)*65 + fgrp ; block = 128 (4 warps = 4 consecutive f)
__global__ __launch_bounds__(128, 6)
void k_main(const float* __restrict__ in, const int* __restrict__ beam_id,
            const float* __restrict__ tw, const float* __restrict__ nw,
            float* __restrict__ out) {
    __shared__ __align__(16) float xs[2][32][68];  // double-buffered staging
    __shared__ float  wsm[4][80];     // per-warp weights: [w][16 targ | 64 null]
    __shared__ float4 q_s[4][34];     // 34-pad: conflict-free staged reads
    __shared__ float2 tg_s[4][34];
    __shared__ int    fs_s[4], fv_s[4];

    int bi    = blockIdx.x;
    int fgrp  = bi % NFG;
    int rem   = bi / NFG;
    int chunk = rem & 3;
    int b     = rem >> 2;

    int tid = threadIdx.x, lane = tid & 31, w = tid >> 5;
    int f0  = fgrp * 4;
    int fv  = (f0 + w) < NF;
    int f   = min(f0 + w, NF-1);
    int beam = beam_id[b];
    bool inb = fv && (f >= LOWF) && (f < HIGHF);

    if (lane == 0) { fs_s[w] = fv ? f : -1; }   // validity in sign bit
    if (lane == 1) { fv_s[w] = fv; }

    // ---- stage weights (once) ----
    if (lane < 16) {
        int part = lane >> 3, c = lane & 7;
        wsm[w][part*8 + c] = tw[((beam*2 + part)*NF + f)*NC + c];
    }
    {
        #pragma unroll
        for (int h = 0; h < 2; h++) {
            int j = lane + h*32;
            int n = j >> 4, ri = (j >> 3) & 1, c = j & 7;
            wsm[w][16 + j] = nw[(((beam*NNUL + n)*2 + ri)*NF + f)*NC + c];
        }
    }
    __syncthreads();

    // ---- hoisted epilogue store indices (constant per thread) ----
    int fD;                 // dcf store f (−1 if invalid)
    int fT0, fT1;           // targ store f's (−1 if invalid)
    {
        int fiD = tid & 3;
        fD = fs_s[fiD];
        int f2T = ((tid & 63) & 1) * 2;
        fT0 = fs_s[f2T];
        fT1 = fs_s[f2T + 1];
    }

    float pa = exp2f((float)(lane+1) * -1.5145732f);   // a^(lane+1)
    float carry[9];
    #pragma unroll
    for (int k = 0; k < 9; k++) carry[k] = 0.0f;

    // ---- per-pass staging constants (4 cp.async tasks per thread) ----
    const int ROWLIM = ROWF - 4;
    int tl_[4];
    uint32_t dst_[4];
    const float* pbase_[4];
    {
        uint32_t xs0 = (uint32_t)__cvta_generic_to_shared(&xs[0][0][0]);
        const float* inb0 = in + (size_t)b*NT*2*ROWF;
        #pragma unroll
        for (int pass = 0; pass < 4; pass++) {
            int i   = pass*128 + tid;       // 0..511
            int seg = i >> 3;
            int tl  = seg >> 1, part = seg & 1, e = i & 7;
            int col = min(f0*NC + e*4, ROWLIM);
            tl_[pass]    = tl;
            dst_[pass]   = xs0 + (uint32_t)(tl*68 + part*32 + e*4)*4;
            pbase_[pass] = inb0 + (size_t)part*ROWF + col;
        }
    }

    int T0 = chunk * 128;
    int itstart = chunk ? -1 : 0;       // it = -1 is warmup (discard)

    // ---- prologue: stage first iteration into buf (itstart & 1) ----
    {
        int tbase = T0 + itstart*32;
        uint32_t bofs = (uint32_t)(itstart & 1) * (XSBUF*4);
        #pragma unroll
        for (int pass = 0; pass < 4; pass++) {
            int tg = min(tbase + tl_[pass], NT-1);
            cp16(dst_[pass] + bofs, pbase_[pass] + (size_t)tg*2*ROWF);
        }
        cp_commit();
    }

    for (int it = itstart; it < 4; it++) {
        int tbase = T0 + it*32;
        int buf   = it & 1;

        // ---- issue next iteration's group (overlaps current compute) ----
        if (it < 3) {
            int tnext = tbase + 32;
            uint32_t bofs = (uint32_t)((it+1) & 1) * (XSBUF*4);
            #pragma unroll
            for (int pass = 0; pass < 4; pass++) {
                int tg = min(tnext + tl_[pass], NT-1);
                cp16(dst_[pass] + bofs, pbase_[pass] + (size_t)tg*2*ROWF);
            }
            cp_commit();
            asm volatile("cp.async.wait_group 1;");
        } else {
            asm volatile("cp.async.wait_group 0;");
        }
        __syncthreads();                // current buffer fully staged, visible

        // ---- beamform from smem ----
        float xr[8], xi[8];
        {
            float4 r0 = *(float4*)&xs[buf][lane][w*8];
            float4 r1 = *(float4*)&xs[buf][lane][w*8 + 4];
            float4 i0 = *(float4*)&xs[buf][lane][32 + w*8];
            float4 i1 = *(float4*)&xs[buf][lane][32 + w*8 + 4];
            xr[0]=r0.x; xr[1]=r0.y; xr[2]=r0.z; xr[3]=r0.w;
            xr[4]=r1.x; xr[5]=r1.y; xr[6]=r1.z; xr[7]=r1.w;
            xi[0]=i0.x; xi[1]=i0.y; xi[2]=i0.z; xi[3]=i0.w;
            xi[4]=i1.x; xi[5]=i1.y; xi[6]=i1.z; xi[7]=i1.w;
        }

        // target weights via uniform smem loads
        float tr=0.f, ti=0.f, pw=0.f;
        {
            float4 a0 = *(float4*)&wsm[w][0], a1 = *(float4*)&wsm[w][4];
            float4 b0 = *(float4*)&wsm[w][8], b1 = *(float4*)&wsm[w][12];
            float twr_[8], twi_[8];
            twr_[0]=a0.x; twr_[1]=a0.y; twr_[2]=a0.z; twr_[3]=a0.w;
            twr_[4]=a1.x; twr_[5]=a1.y; twr_[6]=a1.z; twr_[7]=a1.w;
            twi_[0]=b0.x; twi_[1]=b0.y; twi_[2]=b0.z; twi_[3]=b0.w;
            twi_[4]=b1.x; twi_[5]=b1.y; twi_[6]=b1.z; twi_[7]=b1.w;
            #pragma unroll
            for (int c = 0; c < 8; c++) {
                tr = fmaf(twr_[c], xr[c], tr); tr = fmaf(-twi_[c], xi[c], tr);
                ti = fmaf(twi_[c], xr[c], ti); ti = fmaf( twr_[c], xi[c], ti);
                pw = fmaf(xr[c], xr[c], pw);  pw = fmaf(xi[c], xi[c], pw);
            }
        }
        pw *= 0.125f;

        int t  = tbase + lane;
        int tc = min(t, NT-1);
        float u[9];
        #pragma unroll
        for (int n = 0; n < NNUL; n++) {
            float nwr_[8], nwi_[8];
            {
                float4 c0 = *(float4*)&wsm[w][16 + n*16];
                float4 c1 = *(float4*)&wsm[w][16 + n*16 + 4];
                float4 d0 = *(float4*)&wsm[w][16 + n*16 + 8];
                float4 d1 = *(float4*)&wsm[w][16 + n*16 + 12];
                nwr_[0]=c0.x; nwr_[1]=c0.y; nwr_[2]=c0.z; nwr_[3]=c0.w;
                nwr_[4]=c1.x; nwr_[5]=c1.y; nwr_[6]=c1.z; nwr_[7]=c1.w;
                nwi_[0]=d0.x; nwi_[1]=d0.y; nwi_[2]=d0.z; nwi_[3]=d0.w;
                nwi_[4]=d1.x; nwi_[5]=d1.y; nwi_[6]=d1.z; nwi_[7]=d1.w;
            }
            float nr=0.f, ni=0.f;
            #pragma unroll
            for (int c = 0; c < 8; c++) {
                nr = fmaf(nwr_[c], xr[c], nr); nr = fmaf(-nwi_[c], xi[c], nr);
                ni = fmaf(nwi_[c], xr[c], ni); ni = fmaf( nwr_[c], xi[c], ni);
            }
            float pr = tr*nr + ti*ni;
            float pi = ti*nr - tr*ni;
            if (tc == 0) {   // reference's t=0 quirk (chunk 0, iter 0, lane 0)
                pr = fmaf( AOVER*ti, ni, pr);
                pi = fmaf(-AOVER*tr, ni, pi);
            }
            u[n]   = OMA*pr;
            u[4+n] = OMA*pi;
        }
        u[8] = OMA*pw;

        scan9(u, lane);
        float y[9];
        #pragma unroll
        for (int k = 0; k < 9; k++) y[k] = fmaf(pa, carry[k], u[k]);
        #pragma unroll
        for (int k = 0; k < 9; k++) carry[k] = __shfl_sync(0xffffffffu, y[k], 31);

        if (it < 0) continue;           // warmup: discard (xs buffers disjoint)

        // ---- epilogue: pre-ratio q, band atomics, staged coalesced stores --
        float rinv = __fdividef(1.0f, y[8] + 1e-13f);
        float ph[4], q[4];
        #pragma unroll
        for (int n = 0; n < 4; n++) {
            ph[n] = sqrtf(fmaf(y[n], y[n], y[4+n]*y[4+n]));
            q[n]  = fminf(fmaxf(ph[n]*rinv, 0.01f), 1.0f);
        }
        if (inb && t < NT) {
            atomicAdd(g_pre + b*NT + t, y[8]);
            float* aftp = g_aft + (b*NT + t)*NNUL;
            #pragma unroll
            for (int n = 0; n < 4; n++) atomicAdd(aftp + n, ph[n]);
        }

        q_s[w][lane]  = make_float4(q[0], q[1], q[2], q[3]);
        tg_s[w][lane] = make_float2(tr, ti);
        __syncthreads();                // q_s/tg_s writes visible to readers

        {   // dcf: thread = (t_local, fi) -> 64B contiguous runs
            int tl = tid >> 2, fi = tid & 3;
            int tt = tbase + tl;
            if (fD >= 0 && tt < NT)
                *(float4*)(out + ((size_t)(b*NT + tt)*NF + fD)*4) = q_s[fi][tl];
        }
        {   // targ: thread = (part, t_local, f-pair)
            int p = tid >> 6, r2 = tid & 63, tl2 = r2 >> 1, f2 = (r2 & 1)*2;
            int tt2 = tbase + tl2;
            if (tt2 < NT) {
                size_t base = DCF_SIZE + ((size_t)(b*NT + tt2)*2 + p)*NF;
                if (fT0 >= 0) {
                    float2 v = tg_s[f2][tl2];
                    out[base + fT0] = p ? v.y : v.x;
                }
                if (fT1 >= 0) {
                    float2 v = tg_s[f2+1][tl2];
                    out[base + fT1] = p ? v.y : v.x;
                }
            }
        }
        // q_s reads are fenced by next iteration's wait+syncthreads.
    }
}

// =================== k_rat: ratios + accumulator reset =======================
__global__ __launch_bounds__(256)
void k_rat(void) {
    int idx = blockIdx.x*256 + threadIdx.x;
    if (idx >= NB*NT) return;
    float pre = g_pre[idx];
    float4 af = ((const float4*)g_aft)[idx];
    float pinv = __fdividef(1.0f, pre + 1e-10f);
    float4 r;
    r.x = fminf(fmaxf(af.x*pinv, 0.01f), 1.0f);
    r.y = fminf(fmaxf(af.y*pinv, 0.01f), 1.0f);
    r.z = fminf(fmaxf(af.z*pinv, 0.01f), 1.0f);
    r.w = fminf(fmaxf(af.w*pinv, 0.01f), 1.0f);
    ((float4*)g_rat)[idx] = r;
    g_pre[idx] = 0.0f;
    ((float4*)g_aft)[idx] = make_float4(0.f, 0.f, 0.f, 0.f);
}

// =================== k_fix_flat: streaming ratio apply (t >= 1) ==============
__global__ __launch_bounds__(256)
void k_fix_flat(float* __restrict__ out) {
    int idx = blockIdx.x*256 + threadIdx.x;     // one per (b,t,f)
    if (idx >= NB*NT*NF) return;
    int bt = idx / NF;
    int t  = bt % NT;
    if (t == 0) return;
    float4 rat = ((const float4*)g_rat)[bt];
    float* p = out + (size_t)idx*4;
    float4 q = *(float4*)p;
    q.x = sqrtf(q.x * rat.x);
    q.y = sqrtf(q.y * rat.y);
    q.z = sqrtf(q.z * rat.z);
    q.w = sqrtf(q.w * rat.w);
    *(float4*)p = q;
}

// =================== launcher ===============================================
extern "C" void kernel_launch(void* const* d_in, const int* in_sizes, int n_in,
                              void* d_out, int out_size) {
    const float* in      = (const float*)d_in[0];
    const int*   beam_id = (const int*)  d_in[1];
    const float* tw      = (const float*)d_in[2];
    const float* nw      = (const float*)d_in[3];
    float* out = (float*)d_out;

    k_main<<<NB*NCHUNK*NFG, 128>>>(in, beam_id, tw, nw, out);
    k_rat<<<(NB*NT + 255)/256, 256>>>();
    k_fix_flat<<<(NB*NT*NF + 255)/256, 256>>>(out);
}